// round 1
// baseline (speedup 1.0000x reference)
#include <cuda_runtime.h>
#include <cuda_bf16.h>
#include <cstdint>

// Problem constants (fixed by the reference)
#define EMB    64
#define HEADS  8
#define DIMI   20
#define DIMH   16
#define DIMW   16
#define DIMD   16
#define NQ     4116                  // DIMI + 16*16*16
#define ROWF4  1029                  // 4116 / 4
#define TABR   63                    // 2*CAP - 1
#define INVT   0.125f                // 64^-0.5

// Precomputed small tables (scaling folded in)
__device__ float g_projH[HEADS * TABR];   // * INVT/3
__device__ float g_projW[HEADS * TABR];
__device__ float g_projD[HEADS * TABR];
__device__ float g_cross[HEADS * DIMI];   // * INVT

__global__ void prep_kernel(const float* __restrict__ enc_cross,
                            const float* __restrict__ enc_h,
                            const float* __restrict__ enc_w,
                            const float* __restrict__ enc_d,
                            const float* __restrict__ w_cross,
                            const float* __restrict__ w_h,
                            const float* __restrict__ w_w,
                            const float* __restrict__ w_d) {
    const int NPROJ = 3 * HEADS * TABR;           // 1512
    const int NTOT  = NPROJ + HEADS * DIMI;       // + 160
    for (int item = threadIdx.x; item < NTOT; item += blockDim.x) {
        if (item < NPROJ) {
            int axis = item / (HEADS * TABR);
            int rem  = item - axis * (HEADS * TABR);
            int h = rem / TABR, r = rem - h * TABR;
            const float* tab = (axis == 0) ? enc_h : (axis == 1) ? enc_w : enc_d;
            const float* w   = (axis == 0) ? w_h   : (axis == 1) ? w_w   : w_d;
            float s = 0.f;
            #pragma unroll
            for (int c = 0; c < EMB; c++) s += w[h * EMB + c] * tab[r * EMB + c];
            float v = s * (INVT / 3.0f);
            float* dst = (axis == 0) ? g_projH : (axis == 1) ? g_projW : g_projD;
            dst[h * TABR + r] = v;
        } else {
            int rem = item - NPROJ;
            int h = rem / DIMI, n = rem - h * DIMI;
            float s = 0.f;
            #pragma unroll
            for (int c = 0; c < EMB; c++) s += w_cross[h * EMB + c] * enc_cross[n * EMB + c];
            g_cross[h * DIMI + n] = s * INVT;
        }
    }
}

// One block per output row (h, q). 256 threads, float4 stores.
__global__ __launch_bounds__(256)
void scores_kernel(float* __restrict__ out) {
    const int bid = blockIdx.x;              // h * NQ + q
    const int h = bid / NQ;
    const int q = bid - h * NQ;
    float4* __restrict__ row = reinterpret_cast<float4*>(out + (size_t)bid * NQ);
    const int t = threadIdx.x;

    if (q < DIMI) {
        // zero row
        const float4 z = make_float4(0.f, 0.f, 0.f, 0.f);
        for (int f = t; f < ROWF4; f += 256) row[f] = z;
        return;
    }

    __shared__ float sa[16], sb[16], sc[16], scr[DIMI];
    const int srow = q - DIMI;
    const int i  = srow >> 8;
    const int j  = (srow >> 4) & 15;
    const int k3 = srow & 15;

    if (t < 16)       sa[t]        = g_projH[h * TABR + (t)        - i  + 31];
    else if (t < 32)  sb[t - 16]   = g_projW[h * TABR + (t - 16)   - j  + 31];
    else if (t < 48)  sc[t - 32]   = g_projD[h * TABR + (t - 32)   - k3 + 31];
    else if (t < 48 + DIMI) scr[t - 48] = g_cross[h * DIMI + (t - 48)];
    __syncthreads();

    for (int f = t; f < ROWF4; f += 256) {
        float4 v;
        if (f < 5) {
            // k = 4f .. 4f+3  (cross block, exactly 20 = 5 float4s)
            v.x = scr[4 * f + 0];
            v.y = scr[4 * f + 1];
            v.z = scr[4 * f + 2];
            v.w = scr[4 * f + 3];
        } else {
            const int scol = 4 * f - DIMI;           // multiple of 4
            const int l  = scol >> 8;
            const int m  = (scol >> 4) & 15;
            const int n0 = scol & 15;                // 0,4,8,12 -> n0+3 <= 15
            const float base = sa[l] + sb[m];
            v.x = base + sc[n0 + 0];
            v.y = base + sc[n0 + 1];
            v.z = base + sc[n0 + 2];
            v.w = base + sc[n0 + 3];
        }
        row[f] = v;
    }
}

extern "C" void kernel_launch(void* const* d_in, const int* in_sizes, int n_in,
                              void* d_out, int out_size) {
    const float* enc_cross = (const float*)d_in[0];
    const float* enc_h     = (const float*)d_in[1];
    const float* enc_w     = (const float*)d_in[2];
    const float* enc_d     = (const float*)d_in[3];
    const float* w_cross   = (const float*)d_in[4];
    const float* w_h       = (const float*)d_in[5];
    const float* w_w       = (const float*)d_in[6];
    const float* w_d       = (const float*)d_in[7];
    float* out = (float*)d_out;

    prep_kernel<<<1, 256>>>(enc_cross, enc_h, enc_w, enc_d,
                            w_cross, w_h, w_w, w_d);
    scores_kernel<<<HEADS * NQ, 256>>>(out);
}

// round 2
// speedup vs baseline: 1.7088x; 1.7088x over previous
#include <cuda_runtime.h>
#include <cuda_bf16.h>
#include <cstdint>

// Problem constants (fixed by the reference)
#define EMB    64
#define HEADS  8
#define DIMI   20
#define NQ     4116                  // DIMI + 16*16*16
#define ROWF4  1029                  // 4116 / 4
#define TABR   63                    // 2*CAP - 1
#define INVT   0.125f                // 64^-0.5

#define NPROJ  (3 * HEADS * TABR)    // 1512
#define NCROSS (HEADS * DIMI)        // 160
#define NITEMS (NPROJ + NCROSS)      // 1672

// Precomputed small tables (scaling folded in)
__device__ float g_projH[HEADS * TABR];   // * INVT/3
__device__ float g_projW[HEADS * TABR];
__device__ float g_projD[HEADS * TABR];
__device__ float g_cross[HEADS * DIMI];   // * INVT

// One warp per output scalar: lane c handles elements c and c+32 of the
// 64-length dot product, then butterfly-reduce.
__global__ __launch_bounds__(256)
void prep_kernel(const float* __restrict__ enc_cross,
                 const float* __restrict__ enc_h,
                 const float* __restrict__ enc_w,
                 const float* __restrict__ enc_d,
                 const float* __restrict__ w_cross,
                 const float* __restrict__ w_h,
                 const float* __restrict__ w_w,
                 const float* __restrict__ w_d) {
    const int warp = blockIdx.x * 8 + (threadIdx.x >> 5);
    const int lane = threadIdx.x & 31;
    if (warp >= NITEMS) return;

    const float* vec;   // [*, EMB] row
    const float* w;     // [HEADS, EMB] row
    float scale;
    float* dst;

    if (warp < NPROJ) {
        const int axis = warp / (HEADS * TABR);
        const int rem  = warp - axis * (HEADS * TABR);
        const int h = rem / TABR, r = rem - h * TABR;
        const float* tab = (axis == 0) ? enc_h : (axis == 1) ? enc_w : enc_d;
        const float* wt  = (axis == 0) ? w_h   : (axis == 1) ? w_w   : w_d;
        float* db        = (axis == 0) ? g_projH : (axis == 1) ? g_projW : g_projD;
        vec = tab + r * EMB;
        w   = wt + h * EMB;
        scale = INVT / 3.0f;
        dst = db + h * TABR + r;
    } else {
        const int rem = warp - NPROJ;
        const int h = rem / DIMI, n = rem - h * DIMI;
        vec = enc_cross + n * EMB;
        w   = w_cross + h * EMB;
        scale = INVT;
        dst = g_cross + h * DIMI + n;
    }

    float s = w[lane] * vec[lane] + w[lane + 32] * vec[lane + 32];
    #pragma unroll
    for (int off = 16; off > 0; off >>= 1)
        s += __shfl_xor_sync(0xffffffffu, s, off);
    if (lane == 0) *dst = s * scale;
}

// One block per output row (h, q). 256 threads, float4 streaming stores.
__global__ __launch_bounds__(256)
void scores_kernel(float* __restrict__ out) {
    const int bid = blockIdx.x;              // h * NQ + q
    const int h = bid / NQ;
    const int q = bid - h * NQ;
    float4* __restrict__ row = reinterpret_cast<float4*>(out + (size_t)bid * NQ);
    const int t = threadIdx.x;

    if (q < DIMI) {
        const float4 z = make_float4(0.f, 0.f, 0.f, 0.f);
        for (int f = t; f < ROWF4; f += 256) __stcs(&row[f], z);
        return;
    }

    __shared__ float sa[16], sb[16], sc[16], scr[DIMI];
    const int srow = q - DIMI;
    const int i  = srow >> 8;
    const int j  = (srow >> 4) & 15;
    const int k3 = srow & 15;

    if (t < 16)       sa[t]        = g_projH[h * TABR + (t)        - i  + 31];
    else if (t < 32)  sb[t - 16]   = g_projW[h * TABR + (t - 16)   - j  + 31];
    else if (t < 48)  sc[t - 32]   = g_projD[h * TABR + (t - 32)   - k3 + 31];
    else if (t < 48 + DIMI) scr[t - 48] = g_cross[h * DIMI + (t - 48)];
    __syncthreads();

    for (int f = t; f < ROWF4; f += 256) {
        float4 v;
        if (f < 5) {
            v.x = scr[4 * f + 0];
            v.y = scr[4 * f + 1];
            v.z = scr[4 * f + 2];
            v.w = scr[4 * f + 3];
        } else {
            const int scol = 4 * f - DIMI;           // multiple of 4
            const int l  = scol >> 8;
            const int m  = (scol >> 4) & 15;
            const int n0 = scol & 15;                // 0,4,8,12
            const float base = sa[l] + sb[m];
            v.x = base + sc[n0 + 0];
            v.y = base + sc[n0 + 1];
            v.z = base + sc[n0 + 2];
            v.w = base + sc[n0 + 3];
        }
        __stcs(&row[f], v);
    }
}

extern "C" void kernel_launch(void* const* d_in, const int* in_sizes, int n_in,
                              void* d_out, int out_size) {
    const float* enc_cross = (const float*)d_in[0];
    const float* enc_h     = (const float*)d_in[1];
    const float* enc_w     = (const float*)d_in[2];
    const float* enc_d     = (const float*)d_in[3];
    const float* w_cross   = (const float*)d_in[4];
    const float* w_h       = (const float*)d_in[5];
    const float* w_w       = (const float*)d_in[6];
    const float* w_d       = (const float*)d_in[7];
    float* out = (float*)d_out;

    prep_kernel<<<(NITEMS + 7) / 8, 256>>>(enc_cross, enc_h, enc_w, enc_d,
                                           w_cross, w_h, w_w, w_d);
    scores_kernel<<<HEADS * NQ, 256>>>(out);
}